// round 12
// baseline (speedup 1.0000x reference)
#include <cuda_runtime.h>
#include <cstdint>

#define B_SZ 512
#define T_SZ 128
#define NBLK 144
#define SMEM_PERSIST 223360
#define SMEM_PROJ    61504

// ---------------- __device__ scratch (no allocations allowed) ----------------
// xg0: [t][bn(8)][b(512)][128]
__device__ __align__(128) float g_xg0[(size_t)T_SZ * 8 * B_SZ * 128];
__device__ __align__(128) float g_xg1[(size_t)T_SZ * B_SZ * 256];
__device__ __align__(128) float g_xg2[(size_t)T_SZ * B_SZ * 256];
// xp: [kt][row(65536)][20]  (16 quad-swizzled k-values + 4 pad)
__device__ __align__(128) float g_xp0[(size_t)19 * 65536 * 20];
__device__ __align__(128) float g_xp1[(size_t)5 * 65536 * 20];
__device__ __align__(128) float g_xp2[(size_t)3 * 65536 * 20];
// wih: [kt][gate][20]
__device__ __align__(128) float g_wih0[19 * 1024 * 20];
__device__ __align__(128) float g_wih1[5 * 256 * 20];
__device__ __align__(128) float g_wih2[3 * 256 * 20];
__device__ __align__(128) float g_whh0[1024 * 256];   // [gate][256], K pair-swizzled
__device__ __align__(128) float g_whh1[256 * 64];
__device__ __align__(128) float g_whh2[256 * 64];
__device__ __align__(128) float g_bias0[1024];
__device__ __align__(128) float g_bias1[256];
__device__ __align__(128) float g_bias2[256];
// h0: row-padded (264) so a 16-row half-tile is ONE contiguous bulk copy
__device__ __align__(128) float g_h0[2][B_SZ * 264];  // tf32, pair-swizzled
__device__ __align__(128) float g_h1[B_SZ * 72];      // final h only (written at t=127)
__device__ __align__(128) float g_h2[B_SZ * 72];
__device__ __align__(128) unsigned g_bar0[16 * 128];  // [bm][t] step barriers, target 8

// ---------------- helpers ----------------
__device__ __forceinline__ int swz(int k) {          // 8-group pair swizzle (h / whh)
    return (k & ~7) | ((k & 3) << 1) | ((k >> 2) & 1);
}
__device__ __forceinline__ int swz16q(int k) {       // 16-group quad swizzle (xp / wih)
    return ((k & 3) << 2) | ((k >> 3) << 1) | ((k >> 2) & 1);
}

__device__ __forceinline__ float tf32r(float x) {
    uint32_t u;
    asm("cvt.rna.tf32.f32 %0, %1;" : "=r"(u) : "f"(x));
    return __uint_as_float(u);
}

__device__ __forceinline__ void mma_tf32(float c[4], const uint32_t a[4], const uint32_t b[2]) {
    asm volatile(
        "mma.sync.aligned.m16n8k8.row.col.f32.tf32.tf32.f32 "
        "{%0,%1,%2,%3}, {%4,%5,%6,%7}, {%8,%9}, {%0,%1,%2,%3};"
        : "+f"(c[0]), "+f"(c[1]), "+f"(c[2]), "+f"(c[3])
        : "r"(a[0]), "r"(a[1]), "r"(a[2]), "r"(a[3]), "r"(b[0]), "r"(b[1]));
}

__device__ __forceinline__ float fex2(float x) {
    float r; asm("ex2.approx.f32 %0, %1;" : "=f"(r) : "f"(x)); return r;
}
__device__ __forceinline__ float frcp(float x) {
    float r; asm("rcp.approx.f32 %0, %1;" : "=f"(r) : "f"(x)); return r;
}
__device__ __forceinline__ float sigm(float x) {
    return frcp(1.0f + fex2(-1.4426950408889634f * x));
}
__device__ __forceinline__ float tanhfast(float x) {
    return 2.0f * frcp(1.0f + fex2(-2.8853900817779268f * x)) - 1.0f;
}

// release add (no return) + acquire load: fence-free producer/consumer flag
__device__ __forceinline__ void atom_release_add(unsigned* p) {
    asm volatile("red.release.gpu.global.add.u32 [%0], 1;" :: "l"(p) : "memory");
}
__device__ __forceinline__ unsigned ld_acquire(const unsigned* p) {
    unsigned v;
    asm volatile("ld.acquire.gpu.global.u32 %0, [%1];" : "=r"(v) : "l"(p) : "memory");
    return v;
}

// ---- bulk-copy + mbarrier primitives ----
__device__ __forceinline__ uint32_t s2u(const void* p) {
    return (uint32_t)__cvta_generic_to_shared(p);
}
__device__ __forceinline__ void mbar_init(uint32_t mb, uint32_t cnt) {
    asm volatile("mbarrier.init.shared.b64 [%0], %1;" :: "r"(mb), "r"(cnt) : "memory");
}
__device__ __forceinline__ void mbar_arrive_tx(uint32_t mb, uint32_t bytes) {
    asm volatile("mbarrier.arrive.expect_tx.shared.b64 _, [%0], %1;"
                 :: "r"(mb), "r"(bytes) : "memory");
}
__device__ __forceinline__ void mbar_wait(uint32_t mb, uint32_t parity) {
    asm volatile(
        "{\n\t.reg .pred P;\n"
        "W%=:\n\t"
        "mbarrier.try_wait.parity.shared.b64 P, [%0], %1;\n\t"
        "@!P bra W%=;\n\t}"
        :: "r"(mb), "r"(parity) : "memory");
}
__device__ __forceinline__ void bulk_g2s(uint32_t dst, const void* src,
                                         uint32_t bytes, uint32_t mb) {
    asm volatile(
        "cp.async.bulk.shared::cluster.global.mbarrier::complete_tx::bytes "
        "[%0], [%1], %2, [%3];"
        :: "r"(dst), "l"(src), "r"(bytes), "r"(mb) : "memory");
}
#define FENCE_ASYNC asm volatile("fence.proxy.async.shared::cta;" ::: "memory")

// ---------------- launch 0: prep weights ----------------
__global__ void prep_w_kernel(
    const float* __restrict__ wih0, const float* __restrict__ whh0,
    const float* __restrict__ bih0, const float* __restrict__ bhh0,
    const float* __restrict__ wih1, const float* __restrict__ whh1,
    const float* __restrict__ bih1, const float* __restrict__ bhh1,
    const float* __restrict__ wih2, const float* __restrict__ whh2,
    const float* __restrict__ bih2, const float* __restrict__ bhh2)
{
    size_t stride = (size_t)gridDim.x * blockDim.x;
    size_t t0 = (size_t)blockIdx.x * blockDim.x + threadIdx.x;

    for (size_t ii = t0; ii < 1024 * 304; ii += stride) {
        int i = (int)ii;
        int gp = i / 304, dp = i - gp * 304;
        int k = gp >> 2, q = gp & 3, go = q * 256 + k;
        g_wih0[((size_t)(dp >> 4) * 1024 + gp) * 20 + swz16q(dp & 15)] =
            (dp < 300) ? tf32r(wih0[go * 300 + dp]) : 0.0f;
    }
    for (size_t ii = t0; ii < 256 * 80; ii += stride) {
        int i = (int)ii;
        int gp = i / 80, dp = i - gp * 80;
        int k = gp >> 2, q = gp & 3, go = q * 64 + k;
        g_wih1[((size_t)(dp >> 4) * 256 + gp) * 20 + swz16q(dp & 15)] =
            (dp < 74) ? tf32r(wih1[go * 74 + dp]) : 0.0f;
    }
    for (size_t ii = t0; ii < 256 * 48; ii += stride) {
        int i = (int)ii;
        int gp = i / 48, dp = i - gp * 48;
        int k = gp >> 2, q = gp & 3, go = q * 64 + k;
        g_wih2[((size_t)(dp >> 4) * 256 + gp) * 20 + swz16q(dp & 15)] =
            (dp < 35) ? tf32r(wih2[go * 35 + dp]) : 0.0f;
    }
    for (size_t ii = t0; ii < 1024 * 256; ii += stride) {
        int i = (int)ii;
        int gp = i >> 8, dp = i & 255;
        int k = gp >> 2, q = gp & 3, go = q * 256 + k;
        g_whh0[gp * 256 + swz(dp)] = tf32r(whh0[go * 256 + dp]);
    }
    for (size_t ii = t0; ii < 256 * 64; ii += stride) {
        int i = (int)ii;
        int gp = i >> 6, dp = i & 63;
        int k = gp >> 2, q = gp & 3, go = q * 64 + k;
        g_whh1[gp * 64 + swz(dp)] = tf32r(whh1[go * 64 + dp]);
        g_whh2[gp * 64 + swz(dp)] = tf32r(whh2[go * 64 + dp]);
    }
    for (size_t ii = t0; ii < 1024; ii += stride) {
        int i = (int)ii;
        int k = i >> 2, q = i & 3, go = q * 256 + k;
        g_bias0[i] = bih0[go] + bhh0[go];
    }
    for (size_t ii = t0; ii < 256; ii += stride) {
        int i = (int)ii;
        int k = i >> 2, q = i & 3, go = q * 64 + k;
        g_bias1[i] = bih1[go] + bhh1[go];
        g_bias2[i] = bih2[go] + bhh2[go];
    }
}

// ---------------- launch 1: pad x -> xp + init state/barriers ----------------
__device__ __forceinline__ void prep_x_one(
    const float* __restrict__ X, float* __restrict__ XP,
    int D, int KT, size_t task0, size_t stride)
{
    size_t ntask = (size_t)KT * 65536;
    for (size_t i = task0; i < ntask; i += stride) {
        int kt = (int)(i >> 16);
        int r = (int)(i & 65535);
        int k0 = kt * 16;
        float o[20];
#pragma unroll
        for (int c = 0; c < 16; c++) {
            int d = k0 + c;
            o[swz16q(c)] = (d < D) ? tf32r(X[(size_t)r * D + d]) : 0.0f;
        }
        o[16] = o[17] = o[18] = o[19] = 0.0f;
        float4* dst = (float4*)&XP[i * 20];
#pragma unroll
        for (int v = 0; v < 5; v++) dst[v] = *(float4*)&o[v * 4];
    }
}

__global__ void prep_x_kernel(
    const float* __restrict__ x0, const float* __restrict__ x1, const float* __restrict__ x2)
{
    size_t stride = (size_t)gridDim.x * blockDim.x;
    size_t t0 = (size_t)blockIdx.x * blockDim.x + threadIdx.x;
    prep_x_one(x0, g_xp0, 300, 19, t0, stride);
    prep_x_one(x1, g_xp1, 74, 5, t0, stride);
    prep_x_one(x2, g_xp2, 35, 3, t0, stride);
    for (size_t i = t0; i < B_SZ * 264; i += stride) g_h0[0][i] = 0.0f;
    for (size_t i = t0; i < 16 * 128; i += stride) g_bar0[i] = 0u;
}

// ---------------- launch 2: projections, 128x128 tiles, LDS.128 fragments ----------
__device__ __forceinline__ void proj_impl(
    const float* __restrict__ XP, const float* __restrict__ W,
    const float* __restrict__ bias, float* __restrict__ XG,
    int G, int KT, int colBase, int rowBase, float* psm)
{
    int tid = threadIdx.x, lane = tid & 31, warp = tid >> 5;
    int gp = lane >> 2, tg = lane & 3;
    int wm = warp >> 1, wn = warp & 1; // 4m x 2n warps; warp tile 32 x 64

    uint32_t mb = s2u(psm);       // 3 mbarriers
    float* buf = psm + 32;

    if (tid == 0) {
        mbar_init(mb, 1); mbar_init(mb + 8, 1); mbar_init(mb + 16, 1);
        FENCE_ASYNC;
    }
    __syncthreads();

    float acc[2][8][4];
#pragma unroll
    for (int i = 0; i < 2; i++)
#pragma unroll
        for (int j = 0; j < 8; j++)
#pragma unroll
            for (int v = 0; v < 4; v++) acc[i][j][v] = 0.0f;

    auto issue = [&](int kt, int s) {
        if (tid == 0) {
            float* xd = buf + s * 5120;
            float* wd = xd + 2560;
            uint32_t m = mb + 8u * s;
            mbar_arrive_tx(m, 20480);
            bulk_g2s(s2u(xd), XP + ((size_t)kt * 65536 + rowBase) * 20, 10240, m);
            bulk_g2s(s2u(wd), W + ((size_t)kt * G + colBase) * 20, 10240, m);
        }
    };

    issue(0, 0);
    issue(1, 1);

    for (int kt = 0; kt < KT; kt++) {
        int s = kt % 3;
        mbar_wait(mb + 8u * s, (uint32_t)((kt / 3) & 1));
        float* xb = buf + s * 5120;
        float* wb = xb + 2560;

        uint32_t a[2][2][4]; // [kk][mt]
#pragma unroll
        for (int mt = 0; mt < 2; mt++) {
            int ar = (wm * 32 + mt * 16 + gp) * 20 + tg * 4;
            float4 lo = *(float4*)&xb[ar];
            float4 hi = *(float4*)&xb[ar + 160];
            a[0][mt][0] = __float_as_uint(lo.x); a[0][mt][1] = __float_as_uint(hi.x);
            a[0][mt][2] = __float_as_uint(lo.y); a[0][mt][3] = __float_as_uint(hi.y);
            a[1][mt][0] = __float_as_uint(lo.z); a[1][mt][1] = __float_as_uint(hi.z);
            a[1][mt][2] = __float_as_uint(lo.w); a[1][mt][3] = __float_as_uint(hi.w);
        }
#pragma unroll
        for (int nt = 0; nt < 8; nt++) {
            int br = (wn * 64 + nt * 8 + gp) * 20 + tg * 4;
            float4 bv = *(float4*)&wb[br];
            uint32_t b0[2] = {__float_as_uint(bv.x), __float_as_uint(bv.y)};
            uint32_t b1[2] = {__float_as_uint(bv.z), __float_as_uint(bv.w)};
#pragma unroll
            for (int mt = 0; mt < 2; mt++) mma_tf32(acc[mt][nt], a[0][mt], b0);
#pragma unroll
            for (int mt = 0; mt < 2; mt++) mma_tf32(acc[mt][nt], a[1][mt], b1);
        }
        __syncthreads();
        if (kt + 2 < KT) issue(kt + 2, (kt + 2) % 3);
    }

#pragma unroll
    for (int mt = 0; mt < 2; mt++)
#pragma unroll
        for (int nt = 0; nt < 8; nt++) {
            int r0 = rowBase + wm * 32 + mt * 16 + gp;
            int col = colBase + wn * 64 + nt * 8 + 2 * tg;
            float bx = bias[col], by = bias[col + 1];
            int tt0 = r0 & 127, bb0 = r0 >> 7;
            int r1 = r0 + 8;
            int tt1 = r1 & 127, bb1 = r1 >> 7;
            size_t o0, o1;
            if (G == 1024) {
                int bnn = col >> 7, cl = col & 127;
                o0 = (((size_t)tt0 * 8 + bnn) * B_SZ + bb0) * 128 + cl;
                o1 = (((size_t)tt1 * 8 + bnn) * B_SZ + bb1) * 128 + cl;
            } else {
                o0 = ((size_t)tt0 * B_SZ + bb0) * 256 + col;
                o1 = ((size_t)tt1 * B_SZ + bb1) * 256 + col;
            }
            *(float2*)&XG[o0] = make_float2(acc[mt][nt][0] + bx, acc[mt][nt][1] + by);
            *(float2*)&XG[o1] = make_float2(acc[mt][nt][2] + bx, acc[mt][nt][3] + by);
        }
}

__global__ __launch_bounds__(256, 2) void proj_all_kernel() {
    extern __shared__ __align__(16) float psm[];
    int bx = blockIdx.x;
    int rowBase = blockIdx.y * 128;
    if (bx < 8) {
        proj_impl(g_xp0, g_wih0, g_bias0, g_xg0, 1024, 19, bx * 128, rowBase, psm);
    } else if (bx < 10) {
        proj_impl(g_xp1, g_wih1, g_bias1, g_xg1, 256, 5, (bx - 8) * 128, rowBase, psm);
    } else {
        proj_impl(g_xp2, g_wih2, g_bias2, g_xg2, 256, 3, (bx - 10) * 128, rowBase, psm);
    }
}

// ---------------- launch 3 (ncu capture index): persistent recurrence ----------------
// blocks 0..127  : m0, 32 rows x 128 gate cols; release/acquire 8-block step barrier;
//                  h tile loaded in two row-halves overlapped with the MMA.
// blocks 128..143: m1/m2, self-contained (h in SMEM, c in regs)
__global__ __launch_bounds__(256, 1) void persist_kernel() {
    extern __shared__ __align__(16) float sm[];
    int bid = blockIdx.x, tid = threadIdx.x;
    int lane = tid & 31, warp = tid >> 5;
    int gp = lane >> 2, tg = lane & 3;

    if (bid < 128) {
        // ================= module 0: H=256, G=1024 =================
        int bm = bid >> 3, bn = bid & 7;
        int rowBase = bm * 32, colBase = bn * 128;
        float* hs   = sm + 32;         // 32 x 264 (two 16-row halves)
        float* xbuf = hs + 8448;       // 32 x 128
        float* gsm  = xbuf + 4096;     // 32 x 128
        uint32_t mb_h0 = s2u(sm);      // rows 0..15
        uint32_t mb_h1 = mb_h0 + 8;    // rows 16..31
        uint32_t mb_x  = mb_h0 + 16;

        if (tid == 0) {
            mbar_init(mb_h0, 1); mbar_init(mb_h1, 1); mbar_init(mb_x, 1);
            FENCE_ASYNC;
        }
        __syncthreads();

        // weights resident in registers: warp wn owns cols [wn*16, wn*16+16), all K
        int wn = warp;
        uint32_t breg[32][2][2];
#pragma unroll
        for (int kk = 0; kk < 32; kk++)
#pragma unroll
            for (int nt = 0; nt < 2; nt++) {
                float2 v = *(const float2*)
                    &g_whh0[(size_t)(colBase + wn * 16 + nt * 8 + gp) * 256 + kk * 8 + tg * 2];
                breg[kk][nt][0] = __float_as_uint(v.x);
                breg[kk][nt][1] = __float_as_uint(v.y);
            }

        float creg[4] = {0.0f, 0.0f, 0.0f, 0.0f};

        // prefetch step-0 inputs
        if (tid == 0) {
            mbar_arrive_tx(mb_x, 16384);
            bulk_g2s(s2u(xbuf), g_xg0 + ((size_t)bn * B_SZ + rowBase) * 128, 16384, mb_x);
            const float* hin = g_h0[0];
            mbar_arrive_tx(mb_h0, 16896);
            bulk_g2s(s2u(hs), hin + rowBase * 264, 16896, mb_h0);
            mbar_arrive_tx(mb_h1, 16896);
            bulk_g2s(s2u(hs + 16 * 264), hin + (rowBase + 16) * 264, 16896, mb_h1);
        }

        for (int t = 0; t < T_SZ; t++) {
            float* hout = g_h0[(t & 1) ^ 1];
            uint32_t par = (uint32_t)(t & 1);

            float acc[2][2][4];
#pragma unroll
            for (int i = 0; i < 2; i++)
#pragma unroll
                for (int j = 0; j < 2; j++)
#pragma unroll
                    for (int v = 0; v < 4; v++) acc[i][j][v] = 0.0f;

            // ---- half 1: rows 0..15 (output rows of acc[0]) ----
            mbar_wait(mb_h0, par);
#pragma unroll
            for (int kk = 0; kk < 32; kk++) {
                int kb = kk * 8 + tg * 2;
                float2 lo0 = *(float2*)&hs[gp * 264 + kb];
                float2 hi0 = *(float2*)&hs[(gp + 8) * 264 + kb];
                uint32_t a0[4] = {__float_as_uint(lo0.x), __float_as_uint(hi0.x),
                                  __float_as_uint(lo0.y), __float_as_uint(hi0.y)};
                mma_tf32(acc[0][0], a0, breg[kk][0]);
                mma_tf32(acc[0][1], a0, breg[kk][1]);
            }
            // ---- half 2: rows 16..31 (acc[1]) ----
            mbar_wait(mb_h1, par);
#pragma unroll
            for (int kk = 0; kk < 32; kk++) {
                int kb = kk * 8 + tg * 2;
                float2 lo1 = *(float2*)&hs[(gp + 16) * 264 + kb];
                float2 hi1 = *(float2*)&hs[(gp + 24) * 264 + kb];
                uint32_t a1[4] = {__float_as_uint(lo1.x), __float_as_uint(hi1.x),
                                  __float_as_uint(lo1.y), __float_as_uint(hi1.y)};
                mma_tf32(acc[1][0], a1, breg[kk][0]);
                mma_tf32(acc[1][1], a1, breg[kk][1]);
            }

#pragma unroll
            for (int mt = 0; mt < 2; mt++)
#pragma unroll
                for (int nt = 0; nt < 2; nt++) {
                    int r = mt * 16 + gp, col = wn * 16 + nt * 8 + tg * 2;
                    *(float2*)&gsm[r * 128 + col] =
                        make_float2(acc[mt][nt][0], acc[mt][nt][1]);
                    *(float2*)&gsm[(r + 8) * 128 + col] =
                        make_float2(acc[mt][nt][2], acc[mt][nt][3]);
                }
            __syncthreads();           // gsm ready; all hs reads done
            mbar_wait(mb_x, par);

#pragma unroll
            for (int j = 0; j < 4; j++) {
                int idx = tid + j * 256;
                int bl = idx >> 5, kl = idx & 31;
                float4 gt = *(float4*)&gsm[bl * 128 + 4 * kl];
                float4 xv = *(float4*)&xbuf[bl * 128 + 4 * kl];
                float ii = sigm(gt.x + xv.x);
                float ff = sigm(gt.y + xv.y);
                float gg = tanhfast(gt.z + xv.z);
                float oo = sigm(gt.w + xv.w);
                float cn = ff * creg[j] + ii * gg;
                creg[j] = cn;
                float hn = oo * tanhfast(cn);
                hout[(rowBase + bl) * 264 + swz(bn * 32 + kl)] = tf32r(hn);
            }

            if (t + 1 < T_SZ) {
                __syncthreads();       // all h STGs issued, xbuf reads done
                if (tid == 0) {
                    // xg(t+1): cold DRAM — start before the barrier wait
                    mbar_arrive_tx(mb_x, 16384);
                    bulk_g2s(s2u(xbuf),
                             g_xg0 + (((size_t)(t + 1) * 8 + bn) * B_SZ + rowBase) * 128,
                             16384, mb_x);
                    // release-arrive; acquire-spin (no explicit fences)
                    unsigned* c = &g_bar0[bm * 128 + t];
                    atom_release_add(c);
                    while (ld_acquire(c) < 8u) {}
                    if (bn == 0 && t > 0) g_bar0[bm * 128 + t - 1] = 0u;
                    // h(t+1) immediately — other warps are already parked on mb_h0/mb_h1
                    const float* hin = g_h0[(t + 1) & 1];
                    mbar_arrive_tx(mb_h0, 16896);
                    bulk_g2s(s2u(hs), hin + rowBase * 264, 16896, mb_h0);
                    mbar_arrive_tx(mb_h1, 16896);
                    bulk_g2s(s2u(hs + 16 * 264), hin + (rowBase + 16) * 264, 16896, mb_h1);
                }
                // NO __syncthreads: mb_h0/mb_h1 parity waits at loop top enforce the
                // dependency (tid0 issues the loads only after the release/acquire barrier)
            }
        }
        if (tid == 0 && bn == 0) g_bar0[bm * 128 + 126] = 0u;
    } else {
        // ================= modules 1,2: H=64, G=256, fully self-contained ==========
        int sub = bid - 128;
        int mod = sub >> 3, bm = sub & 7;
        int rowBase = bm * 64;
        const float* whh = mod ? g_whh2 : g_whh1;
        const float* xgb = mod ? g_xg2 : g_xg1;
        float* hfin = mod ? g_h2 : g_h1;

        float* ws   = sm + 32;         // 256 x 72
        float* hs   = ws + 18432;      // 64 x 72   (persistent across steps)
        float* gsm  = hs + 4608;       // 64 x 256
        float* xbuf = gsm + 16384;     // 64 x 256
        uint32_t mb_x = s2u(sm);

        if (tid == 0) { mbar_init(mb_x, 1); FENCE_ASYNC; }

        for (int idx = tid; idx < 256 * 16; idx += 256) {
            int r = idx >> 4, c = idx & 15;
            *(float4*)&ws[r * 72 + c * 4] = *(const float4*)&whh[r * 64 + c * 4];
        }
        for (int idx = tid; idx < 64 * 72; idx += 256) hs[idx] = 0.0f;
        __syncthreads();

        float creg[16];
#pragma unroll
        for (int j = 0; j < 16; j++) creg[j] = 0.0f;

        if (tid == 0) {
            mbar_arrive_tx(mb_x, 65536);
            bulk_g2s(s2u(xbuf), xgb + (size_t)rowBase * 256, 65536, mb_x);
        }

        int wm = warp >> 2, wn = warp & 3;

        for (int t = 0; t < T_SZ; t++) {
            float acc[2][8][4];
#pragma unroll
            for (int i = 0; i < 2; i++)
#pragma unroll
                for (int j = 0; j < 8; j++)
#pragma unroll
                    for (int v = 0; v < 4; v++) acc[i][j][v] = 0.0f;

#pragma unroll
            for (int kk = 0; kk < 8; kk++) {
                uint32_t a[2][4];
#pragma unroll
                for (int mt = 0; mt < 2; mt++) {
                    int ar = (wm * 32 + mt * 16 + gp) * 72 + kk * 8 + tg * 2;
                    float2 lo = *(float2*)&hs[ar];
                    float2 hi = *(float2*)&hs[ar + 576];
                    a[mt][0] = __float_as_uint(lo.x);
                    a[mt][1] = __float_as_uint(hi.x);
                    a[mt][2] = __float_as_uint(lo.y);
                    a[mt][3] = __float_as_uint(hi.y);
                }
#pragma unroll
                for (int nt = 0; nt < 8; nt++) {
                    int br = (wn * 64 + nt * 8 + gp) * 72 + kk * 8 + tg * 2;
                    float2 bv = *(float2*)&ws[br];
                    uint32_t b[2] = {__float_as_uint(bv.x), __float_as_uint(bv.y)};
#pragma unroll
                    for (int mt = 0; mt < 2; mt++) mma_tf32(acc[mt][nt], a[mt], b);
                }
            }

#pragma unroll
            for (int mt = 0; mt < 2; mt++)
#pragma unroll
                for (int nt = 0; nt < 8; nt++) {
                    int r = wm * 32 + mt * 16 + gp;
                    int col = wn * 64 + nt * 8 + 2 * tg;
                    *(float2*)&gsm[r * 256 + col] = make_float2(acc[mt][nt][0], acc[mt][nt][1]);
                    *(float2*)&gsm[(r + 8) * 256 + col] = make_float2(acc[mt][nt][2], acc[mt][nt][3]);
                }
            __syncthreads();
            mbar_wait(mb_x, (uint32_t)(t & 1));

#pragma unroll
            for (int j = 0; j < 16; j++) {
                int idx = tid + j * 256;
                int kl = idx & 63, bl = idx >> 6;
                float4 gt = *(float4*)&gsm[bl * 256 + 4 * kl];
                float4 xv = *(float4*)&xbuf[bl * 256 + 4 * kl];
                float ii = sigm(gt.x + xv.x);
                float ff = sigm(gt.y + xv.y);
                float gg = tanhfast(gt.z + xv.z);
                float oo = sigm(gt.w + xv.w);
                float cn = ff * creg[j] + ii * gg;
                creg[j] = cn;
                float hn = tf32r(oo * tanhfast(cn));
                if (t + 1 < T_SZ) {
                    hs[bl * 72 + swz(kl)] = hn;
                } else {
                    hfin[(rowBase + bl) * 72 + swz(kl)] = hn;
                }
            }
            __syncthreads();
            if (tid == 0 && t + 1 < T_SZ) {
                mbar_arrive_tx(mb_x, 65536);
                bulk_g2s(s2u(xbuf),
                         xgb + ((size_t)(t + 1) * B_SZ + rowBase) * 256, 65536, mb_x);
            }
        }
    }
}

// ---------------- launch 4: head ----------------
__global__ void head_kernel(const float* __restrict__ w1, const float* __restrict__ b1,
                            const float* __restrict__ w2, const float* __restrict__ b2,
                            float* __restrict__ out) {
    __shared__ float hc[8 * 384];
    __shared__ float red[256];
    int tid = threadIdx.x;
    int rowBase = blockIdx.x * 8;

    for (int i = tid; i < 8 * 384; i += 256) {
        int r = i / 384, d = i - r * 384;
        int bg = rowBase + r;
        float v;
        if (d < 256)      v = g_h0[0][bg * 264 + swz(d)];
        else if (d < 320) v = g_h1[bg * 72 + swz(d - 256)];
        else              v = g_h2[bg * 72 + swz(d - 320)];
        hc[i] = v;
    }
    __syncthreads();

    for (int pass = 0; pass < 2; pass++) {
        int row = pass * 4 + (tid >> 6);
        int cell = tid & 63;
        const float* wr = w1 + cell * 384;
        const float* hr = hc + row * 384;
        float a = b1[cell];
#pragma unroll 4
        for (int d = 0; d < 384; d++) a += hr[d] * wr[d];
        a = fmaxf(a, 0.0f);
        red[tid] = a * w2[cell];
        __syncthreads();
        if (cell == 0) {
            float s = 0.0f;
#pragma unroll
            for (int j = 0; j < 64; j++) s += red[tid + j];
            out[rowBase + row] = s + b2[0];
        }
        __syncthreads();
    }
}

// ---------------- launch ----------------
extern "C" void kernel_launch(void* const* d_in, const int* in_sizes, int n_in,
                              void* d_out, int out_size) {
    const float* x0    = (const float*)d_in[0];
    const float* x1    = (const float*)d_in[1];
    const float* x2    = (const float*)d_in[2];
    const float* w_ih0 = (const float*)d_in[3];
    const float* w_hh0 = (const float*)d_in[4];
    const float* b_ih0 = (const float*)d_in[5];
    const float* b_hh0 = (const float*)d_in[6];
    const float* w_ih1 = (const float*)d_in[7];
    const float* w_hh1 = (const float*)d_in[8];
    const float* b_ih1 = (const float*)d_in[9];
    const float* b_hh1 = (const float*)d_in[10];
    const float* w_ih2 = (const float*)d_in[11];
    const float* w_hh2 = (const float*)d_in[12];
    const float* b_ih2 = (const float*)d_in[13];
    const float* b_hh2 = (const float*)d_in[14];
    const float* w1    = (const float*)d_in[15];
    const float* b1    = (const float*)d_in[16];
    const float* w2    = (const float*)d_in[17];
    const float* b2    = (const float*)d_in[18];
    float* out = (float*)d_out;

    cudaFuncSetAttribute(persist_kernel, cudaFuncAttributeMaxDynamicSharedMemorySize,
                         SMEM_PERSIST);
    cudaFuncSetAttribute(proj_all_kernel, cudaFuncAttributeMaxDynamicSharedMemorySize,
                         SMEM_PROJ);

    // launch 0
    prep_w_kernel<<<512, 256>>>(w_ih0, w_hh0, b_ih0, b_hh0,
                                w_ih1, w_hh1, b_ih1, b_hh1,
                                w_ih2, w_hh2, b_ih2, b_hh2);
    // launch 1 (includes state init)
    prep_x_kernel<<<1024, 256>>>(x0, x1, x2);
    // launch 2
    proj_all_kernel<<<dim3(12, 512), 256, SMEM_PROJ>>>();
    // launch 3 (ncu capture index)
    persist_kernel<<<NBLK, 256, SMEM_PERSIST>>>();
    // launch 4
    head_kernel<<<64, 256>>>(w1, b1, w2, b2, out);
}